// round 15
// baseline (speedup 1.0000x reference)
#include <cuda_runtime.h>
#include <cuda_bf16.h>

// SEIR Euler — fused producer/consumer, ILP-2 over REGIONS (1KB warp bursts).
//
// Evidence through round 14: achieved write BW is ~5.3-5.6 TB/s across
// occupancies 38-75% -> not supply-limited. Hypothesis: DRAM write
// efficiency limited by 512B scattered bursts. This version makes each
// consumer warp own one chunk for 64 consecutive regions, so its two
// stores per step are ADJACENT -> 1KB contiguous per warp-step.
// All synchronization intra-CTA -> deadlock-free at any residency.

#define CHUNK      32
#define MAX_CHUNKS 32          // fused path supports t <= 1024
#define BPC        64          // regions per CTA (2 producer warps)
#define BLOCK      512
#define NPROD      2

__device__ __forceinline__ float4 seir_step(float4 v, float bh, float gh, float sh)
{
    const float S = v.x, E = v.y, I = v.z, R = v.w;
    const float p = bh * S;
    float4 r;
    r.x = __fmaf_rn(-p, I, S);
    r.y = __fmaf_rn( p, I, __fmaf_rn(-sh, E, E));
    r.z = __fmaf_rn( sh, E, __fmaf_rn(-gh, I, I));
    r.w = __fmaf_rn( gh, I, R);
    return r;
}

__global__ void __launch_bounds__(BLOCK) seir_fused_kernel(
    const float* __restrict__ initial,
    const float* __restrict__ beta,
    const float* __restrict__ gamma,
    const float* __restrict__ sigma,
    float4* __restrict__ out,
    int B, int t)
{
    __shared__ float4   ckpt[MAX_CHUNKS][BPC];
    __shared__ unsigned flags[MAX_CHUNKS];
    __shared__ unsigned work_ctr;

    const int g    = blockIdx.x;
    const int tid  = threadIdx.x;
    const int wid  = tid >> 5;
    const int lane = tid & 31;
    const int nchunks = t / CHUNK;            // exact in fused path
    const int base_b  = g * BPC;

    const float step = 0.5f;
    const float bh = beta[0]  * step;
    const float gh = gamma[0] * step;
    const float sh = sigma[0] * step;

    for (int i = tid; i < MAX_CHUNKS; i += BLOCK) flags[i] = 0u;
    if (tid == 0) work_ctr = 0u;
    __syncthreads();

    volatile unsigned* vflags = flags;

    if (wid < NPROD) {
        // ---- Producers: 2 warps, each chains 32 of the CTA's 64 regions ----
        const int r = wid * 32 + lane;        // region slot 0..63
        const int b = base_b + r;
        float4 v = make_float4(initial[0 * B + b], initial[1 * B + b],
                               initial[2 * B + b], initial[3 * B + b]);
        for (int c = 0; c < nchunks; ++c) {
            ckpt[c][r] = v;
            __stcs(&out[(size_t)c * CHUNK * B + b], v);  // checkpoint out slot
            __syncwarp();
            if (lane == 0) {
                __threadfence_block();
                atomicAdd(&flags[c], 1u);     // chunk ready when count == NPROD
            }
            if (c + 1 < nchunks) {
                #pragma unroll 8
                for (int j = 0; j < CHUNK; ++j)
                    v = seir_step(v, bh, gh, sh);
            }
        }
        // fall through: producers join the consumer pool
    }

    // ---- Consumers (all warps): one chunk x 64 regions per grab ----
    for (;;) {
        unsigned c;
        if (lane == 0) c = atomicAdd(&work_ctr, 1u);
        c = __shfl_sync(0xFFFFFFFFu, c, 0);
        if (c >= (unsigned)nchunks) break;

        while (vflags[c] < (unsigned)NPROD) { }
        __threadfence_block();

        // ILP-2 over regions: lane handles regions lane and lane+32.
        // The two stores per step are ADJACENT -> 1KB contiguous per warp.
        float4 v0 = ckpt[c][lane];
        float4 v1 = ckpt[c][lane + 32];
        size_t i0 = (size_t)c * CHUNK * B + base_b + lane;
        size_t i1 = i0 + 32;
        #pragma unroll
        for (int j = 1; j < CHUNK; ++j) {
            v0 = seir_step(v0, bh, gh, sh);
            v1 = seir_step(v1, bh, gh, sh);
            i0 += B; i1 += B;
            __stcs(&out[i0], v0);
            __stcs(&out[i1], v1);
        }
    }
}

// ---- Fallback two-kernel path (known-good) for generic shapes ----
__global__ void __launch_bounds__(128) seir_ckpt_kernel(
    const float* __restrict__ initial, const float* __restrict__ beta,
    const float* __restrict__ gamma,   const float* __restrict__ sigma,
    float4* __restrict__ out, int B, int t)
{
    const int b = blockIdx.x * blockDim.x + threadIdx.x;
    if (b >= B) return;
    const float step = 0.5f;
    const float bh = beta[0]*step, gh = gamma[0]*step, sh = sigma[0]*step;
    float4 v = make_float4(initial[0*B+b], initial[1*B+b],
                           initial[2*B+b], initial[3*B+b]);
    out[b] = v;
    const int nchunks = (t + CHUNK - 1) / CHUNK;
    for (int c = 1; c < nchunks; ++c) {
        const int base = (c - 1) * CHUNK;
        const int steps = min(CHUNK, t - base);
        for (int j = 0; j < steps; ++j) v = seir_step(v, bh, gh, sh);
        if (c * CHUNK < t) out[(size_t)c * CHUNK * B + b] = v;
    }
}

__global__ void __launch_bounds__(256) seir_store_kernel(
    const float* __restrict__ beta, const float* __restrict__ gamma,
    const float* __restrict__ sigma, float4* __restrict__ out,
    int B, int t)
{
    const int tid = blockIdx.x * blockDim.x + threadIdx.x;
    const int c  = tid / B;
    const int bb = tid - c * B;
    const int n0 = c * CHUNK;
    if (n0 >= t || bb >= B) return;
    const float step = 0.5f;
    const float bh = beta[0]*step, gh = gamma[0]*step, sh = sigma[0]*step;
    size_t idx = (size_t)n0 * B + bb;
    float4 v = out[idx];
    const int nlast = min(n0 + CHUNK, t);
    for (int n = n0 + 1; n < nlast; ++n) {
        v = seir_step(v, bh, gh, sh);
        idx += B;
        __stcs(&out[idx], v);
    }
}

extern "C" void kernel_launch(void* const* d_in, const int* in_sizes, int n_in,
                              void* d_out, int out_size)
{
    const float* initial = (const float*)d_in[0];   // 4*B elements
    const float* beta    = (const float*)d_in[1];
    const float* gamma   = (const float*)d_in[2];
    const float* sigma   = (const float*)d_in[3];

    const int B = in_sizes[0] / 4;
    const int t = (B > 0) ? (out_size / (4 * B)) : 0;
    if (B <= 0 || t <= 0) return;

    const int nchunks = (t + CHUNK - 1) / CHUNK;

    if ((B % BPC) == 0 && (t % CHUNK) == 0 && nchunks <= MAX_CHUNKS) {
        seir_fused_kernel<<<B / BPC, BLOCK>>>(initial, beta, gamma, sigma,
                                              (float4*)d_out, B, t);
    } else {
        const long long total = (long long)nchunks * B;
        seir_ckpt_kernel<<<(B + 127) / 128, 128>>>(initial, beta, gamma, sigma,
                                                   (float4*)d_out, B, t);
        seir_store_kernel<<<(int)((total + 255) / 256), 256>>>(
            beta, gamma, sigma, (float4*)d_out, B, t);
    }
}

// round 16
// speedup vs baseline: 1.1159x; 1.1159x over previous
#include <cuda_runtime.h>
#include <cuda_bf16.h>

// SEIR Euler — fused producer/consumer, work-queue, ILP-2 store streams.
// FINAL (round-10 optimum, 88.1us = ~6.2 TB/s effective store rate).
//
// Evidence (rounds 2-15): the 536MB output stream saturates the chip's
// streaming-write ceiling (~6.0-6.2 TB/s effective). Occupancy (38-87%),
// streams/warp (1-4), burst length (512B-1KB), and CTA count (512-8192)
// were each A/B'd; all roads lead to ~5.3-6.2 TB/s, and this config is the
// measured maximum. Structure: warp 0 runs the serial SEIR chain for the
// CTA's 32 regions, publishing 32-step checkpoints via SMEM flags; all 8
// warps (producer included, once done) pull chunk pairs from a SMEM work
// queue and stream-store the 31 interior steps with 2 independent STG.128
// streams per chain step. All sync intra-CTA -> deadlock-free.

#define CHUNK      32
#define MAX_CHUNKS 32          // fused path supports t <= 1024
#define BPC        32          // regions per CTA (= producer warp lanes)
#define BLOCK      256
#define GRAB       2

__device__ __forceinline__ float4 seir_step(float4 v, float bh, float gh, float sh)
{
    const float S = v.x, E = v.y, I = v.z, R = v.w;
    const float p = bh * S;
    float4 r;
    r.x = __fmaf_rn(-p, I, S);
    r.y = __fmaf_rn( p, I, __fmaf_rn(-sh, E, E));
    r.z = __fmaf_rn( sh, E, __fmaf_rn(-gh, I, I));
    r.w = __fmaf_rn( gh, I, R);
    return r;
}

__global__ void __launch_bounds__(BLOCK) seir_fused_kernel(
    const float* __restrict__ initial,
    const float* __restrict__ beta,
    const float* __restrict__ gamma,
    const float* __restrict__ sigma,
    float4* __restrict__ out,
    int B, int t)
{
    __shared__ float4   ckpt[MAX_CHUNKS][BPC];
    __shared__ unsigned flags[MAX_CHUNKS];
    __shared__ unsigned work_ctr;

    const int g    = blockIdx.x;
    const int tid  = threadIdx.x;
    const int wid  = tid >> 5;
    const int lane = tid & 31;
    const int nchunks = t / CHUNK;            // exact in fused path
    const int base_b  = g * BPC;

    const float step = 0.5f;
    const float bh = beta[0]  * step;
    const float gh = gamma[0] * step;
    const float sh = sigma[0] * step;

    for (int i = tid; i < MAX_CHUNKS; i += BLOCK) flags[i] = 0u;
    if (tid == 0) work_ctr = 0u;
    __syncthreads();

    volatile unsigned* vflags = flags;

    if (wid == 0) {
        // ---- Producer: serial chain for 32 regions, publish checkpoints ----
        const int b = base_b + lane;
        float4 v = make_float4(initial[0 * B + b], initial[1 * B + b],
                               initial[2 * B + b], initial[3 * B + b]);
        for (int c = 0; c < nchunks; ++c) {
            ckpt[c][lane] = v;
            __stcs(&out[(size_t)c * CHUNK * B + b], v);  // checkpoint out slot
            __syncwarp();
            if (lane == 0) { __threadfence_block(); vflags[c] = 1u; }
            if (c + 1 < nchunks) {
                #pragma unroll 8
                for (int j = 0; j < CHUNK; ++j)
                    v = seir_step(v, bh, gh, sh);
            }
        }
        // fall through: producer joins the consumer pool
    }

    // ---- Consumers (all warps): pull chunk pairs from the work queue ----
    for (;;) {
        unsigned base;
        if (lane == 0) base = atomicAdd(&work_ctr, (unsigned)GRAB);
        base = __shfl_sync(0xFFFFFFFFu, base, 0);
        if (base >= (unsigned)nchunks) break;

        const int c0 = (int)base;
        const int c1 = c0 + 1;
        const bool has2 = (c1 < nchunks);

        while (vflags[c0] == 0u) { }
        if (has2) { while (vflags[c1] == 0u) { } }
        __threadfence_block();

        float4 v0 = ckpt[c0][lane];
        size_t i0 = (size_t)c0 * CHUNK * B + base_b + lane;

        if (has2) {
            float4 v1 = ckpt[c1][lane];
            size_t i1 = (size_t)c1 * CHUNK * B + base_b + lane;
            #pragma unroll
            for (int j = 1; j < CHUNK; ++j) {
                v0 = seir_step(v0, bh, gh, sh);
                v1 = seir_step(v1, bh, gh, sh);
                i0 += B; i1 += B;
                __stcs(&out[i0], v0);   // two independent streams per step
                __stcs(&out[i1], v1);
            }
        } else {
            #pragma unroll
            for (int j = 1; j < CHUNK; ++j) {
                v0 = seir_step(v0, bh, gh, sh);
                i0 += B;
                __stcs(&out[i0], v0);
            }
        }
    }
}

// ---- Fallback two-kernel path (known-good) for generic shapes ----
__global__ void __launch_bounds__(128) seir_ckpt_kernel(
    const float* __restrict__ initial, const float* __restrict__ beta,
    const float* __restrict__ gamma,   const float* __restrict__ sigma,
    float4* __restrict__ out, int B, int t)
{
    const int b = blockIdx.x * blockDim.x + threadIdx.x;
    if (b >= B) return;
    const float step = 0.5f;
    const float bh = beta[0]*step, gh = gamma[0]*step, sh = sigma[0]*step;
    float4 v = make_float4(initial[0*B+b], initial[1*B+b],
                           initial[2*B+b], initial[3*B+b]);
    out[b] = v;
    const int nchunks = (t + CHUNK - 1) / CHUNK;
    for (int c = 1; c < nchunks; ++c) {
        const int base = (c - 1) * CHUNK;
        const int steps = min(CHUNK, t - base);
        for (int j = 0; j < steps; ++j) v = seir_step(v, bh, gh, sh);
        if (c * CHUNK < t) out[(size_t)c * CHUNK * B + b] = v;
    }
}

__global__ void __launch_bounds__(256) seir_store_kernel(
    const float* __restrict__ beta, const float* __restrict__ gamma,
    const float* __restrict__ sigma, float4* __restrict__ out,
    int B, int t)
{
    const int tid = blockIdx.x * blockDim.x + threadIdx.x;
    const int c  = tid / B;
    const int bb = tid - c * B;
    const int n0 = c * CHUNK;
    if (n0 >= t || bb >= B) return;
    const float step = 0.5f;
    const float bh = beta[0]*step, gh = gamma[0]*step, sh = sigma[0]*step;
    size_t idx = (size_t)n0 * B + bb;
    float4 v = out[idx];
    const int nlast = min(n0 + CHUNK, t);
    for (int n = n0 + 1; n < nlast; ++n) {
        v = seir_step(v, bh, gh, sh);
        idx += B;
        __stcs(&out[idx], v);
    }
}

extern "C" void kernel_launch(void* const* d_in, const int* in_sizes, int n_in,
                              void* d_out, int out_size)
{
    const float* initial = (const float*)d_in[0];   // 4*B elements
    const float* beta    = (const float*)d_in[1];
    const float* gamma   = (const float*)d_in[2];
    const float* sigma   = (const float*)d_in[3];

    const int B = in_sizes[0] / 4;
    const int t = (B > 0) ? (out_size / (4 * B)) : 0;
    if (B <= 0 || t <= 0) return;

    if ((B % BPC) == 0 && (t % CHUNK) == 0 && (t / CHUNK) <= MAX_CHUNKS) {
        seir_fused_kernel<<<B / BPC, BLOCK>>>(initial, beta, gamma, sigma,
                                              (float4*)d_out, B, t);
    } else {
        const int nchunks = (t + CHUNK - 1) / CHUNK;
        const long long total = (long long)nchunks * B;
        seir_ckpt_kernel<<<(B + 127) / 128, 128>>>(initial, beta, gamma, sigma,
                                                   (float4*)d_out, B, t);
        seir_store_kernel<<<(int)((total + 255) / 256), 256>>>(
            beta, gamma, sigma, (float4*)d_out, B, t);
    }
}